// round 6
// baseline (speedup 1.0000x reference)
#include <cuda_runtime.h>
#include <math.h>

// Problem constants
#define BB 64
#define TT 512
#define II 128
#define HH 512
#define OO 64
#define ALPHA 0.1f

// Recurrent config: grid 128 = 8 j-slices x 16 batch-blocks.
// Cluster = 8 consecutive CTAs = the 8 j-slices of one batch-block.
// CTA owns 64 j x 4 batches; 16 warps, warp tile = 4j x 4b; lanes partition k 32-way.
#define GRID_R 128
#define NTH_R 512
#define CLUSTER_Q 8
#define BPC 4     // batches per CTA / cluster

__device__ float g_hist[(size_t)TT * BB * HH];   // write-only in recurrence; read by output GEMM

__device__ __forceinline__ float fast_tanh(float v) {
    float e = __expf(2.0f * v);
    return (e - 1.0f) / (e + 1.0f);
}
__device__ __forceinline__ unsigned smem_u32(const void* p) {
    return (unsigned)__cvta_generic_to_shared(p);
}
__device__ __forceinline__ void st_cluster_f32(unsigned laddr, int rank, float val) {
    unsigned raddr;
    asm volatile("mapa.shared::cluster.u32 %0, %1, %2;" : "=r"(raddr) : "r"(laddr), "r"(rank));
    asm volatile("st.shared::cluster.u32 [%0], %1;" :: "r"(raddr), "r"(__float_as_uint(val)));
}
#define CLUSTER_SYNC() do { \
    asm volatile("barrier.cluster.arrive.aligned;" ::: "memory"); \
    asm volatile("barrier.cluster.wait.aligned;"   ::: "memory"); \
} while (0)

__global__ void __launch_bounds__(NTH_R, 1) __cluster_dims__(CLUSTER_Q, 1, 1)
rnn_recurrent(
    const float* __restrict__ x,     // [B][T][I]
    const float* __restrict__ h0,    // [B][H]
    const float* __restrict__ Win,   // [H][I]
    const float* __restrict__ Wrec,  // [H][H]
    const float* __restrict__ bias)  // [H]
{
    __shared__ float sh_h[2][BPC][HH];   // double-buffered h for this batch-block (16 KB)
    __shared__ float sh_x[2][BPC][II];   // double-buffered x_t (4 KB)

    const int tid  = threadIdx.x;
    const int warp = tid >> 5;
    const int lane = tid & 31;

    const int jb   = blockIdx.x & 7;    // j-slice (cluster rank)
    const int bblk = blockIdx.x >> 3;   // batch-block (cluster id)
    const int j0   = jb * 64;
    const int b0   = bblk * BPC;

    const int jbase = warp * 4;         // warp's 4 j's (local 0..60)

    // ---- Preload weights into registers ONCE ----
    float4 wr[4][4];  // wr[jj][c] = Wrec[j0+jbase+jj][c*128 + lane*4 ..]
    float4 wi[4];     // wi[jj]    = Win [j0+jbase+jj][lane*4 ..]
#pragma unroll
    for (int jj = 0; jj < 4; jj++) {
        const float* wrow = Wrec + (size_t)(j0 + jbase + jj) * HH;
#pragma unroll
        for (int c = 0; c < 4; c++)
            wr[jj][c] = *reinterpret_cast<const float4*>(wrow + c * 128 + lane * 4);
        wi[jj] = *reinterpret_cast<const float4*>(Win + (size_t)(j0 + jbase + jj) * II + lane * 4);
    }

    // Epilogue ownership: after log-halving reduction lane L holds full sum of
    // v[idx], idx = 8*b0 + 4*b1 + 2*b2 + b3 (bits of lane); lanes L and L^16 duplicate.
    const int e = lane & 15;
    const int bb_e = 2 * (e & 1) + ((e >> 1) & 1);
    const int jj_e = 2 * ((e >> 2) & 1) + ((e >> 3) & 1);
    const int jh   = j0 + jbase + jj_e;            // index into sh_h's 512-wide j dim
    const float bj = bias[jh];
    float* histp = g_hist + (size_t)(b0 + bb_e) * HH + jh;  // + t*BB*HH per step
    const unsigned laddr_h[2] = { smem_u32(&sh_h[0][bb_e][jh]),
                                  smem_u32(&sh_h[1][bb_e][jh]) };
    const int rbase = (lane >= 16) ? 4 : 0;

    // ---- Prologue: stage h0 and x0 into buffer 0 ----
    {
        int row = tid >> 7, c4 = tid & 127;        // 512 float4 of h0 slice
        float4 v4 = __ldg(reinterpret_cast<const float4*>(h0 + (size_t)(b0 + row) * HH + c4 * 4));
        *reinterpret_cast<float4*>(&sh_h[0][row][c4 * 4]) = v4;
        if (tid < 128) {
            int xrow = tid >> 5, xc4 = tid & 31;   // 128 float4 of x_0 slice
            float4 xv = __ldg(reinterpret_cast<const float4*>(
                x + ((size_t)(b0 + xrow) * TT + 0) * II + xc4 * 4));
            *reinterpret_cast<float4*>(&sh_x[0][xrow][xc4 * 4]) = xv;
        }
    }
    __syncthreads();

    const int xrow = tid >> 5, xc4 = tid & 31;     // x-prefetch roles (tid<128)
    float4 xreg;

    for (int t = 0; t < TT; ++t) {
        const int hb = t & 1;

        // prefetch x_{t+1}
        if (tid < 128 && t + 1 < TT)
            xreg = __ldg(reinterpret_cast<const float4*>(
                x + ((size_t)(b0 + xrow) * TT + (t + 1)) * II + xc4 * 4));

        // ---- Compute: v[bb*4+jj] over this lane's k-set ----
        float v[16];
#pragma unroll
        for (int i = 0; i < 16; i++) v[i] = 0.0f;

#pragma unroll
        for (int bb = 0; bb < 4; bb++) {
#pragma unroll
            for (int c = 0; c < 4; c++) {
                float4 hv = *reinterpret_cast<const float4*>(&sh_h[hb][bb][c * 128 + lane * 4]);
#pragma unroll
                for (int jj = 0; jj < 4; jj++) {
                    v[bb * 4 + jj] = fmaf(hv.x, wr[jj][c].x, v[bb * 4 + jj]);
                    v[bb * 4 + jj] = fmaf(hv.y, wr[jj][c].y, v[bb * 4 + jj]);
                    v[bb * 4 + jj] = fmaf(hv.z, wr[jj][c].z, v[bb * 4 + jj]);
                    v[bb * 4 + jj] = fmaf(hv.w, wr[jj][c].w, v[bb * 4 + jj]);
                }
            }
            float4 xv = *reinterpret_cast<const float4*>(&sh_x[hb][bb][lane * 4]);
#pragma unroll
            for (int jj = 0; jj < 4; jj++) {
                v[bb * 4 + jj] = fmaf(xv.x, wi[jj].x, v[bb * 4 + jj]);
                v[bb * 4 + jj] = fmaf(xv.y, wi[jj].y, v[bb * 4 + jj]);
                v[bb * 4 + jj] = fmaf(xv.z, wi[jj].z, v[bb * 4 + jj]);
                v[bb * 4 + jj] = fmaf(xv.w, wi[jj].w, v[bb * 4 + jj]);
            }
        }

        // ---- Log-halving reduction (16 shfls; R2-proven mapping) ----
#pragma unroll
        for (int i = 0; i < 8; i++) {
            float send = (lane & 1) ? v[i] : v[i + 8];
            float r = __shfl_xor_sync(0xffffffffu, send, 1);
            v[i] = ((lane & 1) ? v[i + 8] : v[i]) + r;
        }
#pragma unroll
        for (int i = 0; i < 4; i++) {
            float send = (lane & 2) ? v[i] : v[i + 4];
            float r = __shfl_xor_sync(0xffffffffu, send, 2);
            v[i] = ((lane & 2) ? v[i + 4] : v[i]) + r;
        }
#pragma unroll
        for (int i = 0; i < 2; i++) {
            float send = (lane & 4) ? v[i] : v[i + 2];
            float r = __shfl_xor_sync(0xffffffffu, send, 4);
            v[i] = ((lane & 4) ? v[i + 2] : v[i]) + r;
        }
        {
            float send = (lane & 8) ? v[0] : v[1];
            float r = __shfl_xor_sync(0xffffffffu, send, 8);
            v[0] = ((lane & 8) ? v[1] : v[0]) + r;
        }
        v[0] += __shfl_xor_sync(0xffffffffu, v[0], 16);  // lanes L and L^16 now identical

        // ---- Epilogue (all 32 lanes; L and L^16 duplicate the value) ----
        {
            float hold = sh_h[hb][bb_e][jh];
            float pre  = v[0] + bj;
            float hnew = (1.0f - ALPHA) * hold + ALPHA * fast_tanh(pre);
            if (lane < 16)
                __stcg(histp + (size_t)t * BB * HH, hnew);
            if (t < TT - 1) {
                // fan h_new out to all 8 cluster CTAs' next buffer (4 ranks per lane)
                unsigned la = laddr_h[hb ^ 1];
#pragma unroll
                for (int r = 0; r < 4; r++)
                    st_cluster_f32(la, rbase + r, hnew);
            }
        }

        // stage x_{t+1} into the other x buffer (no sync needed: double-buffered)
        if (tid < 128 && t + 1 < TT)
            *reinterpret_cast<float4*>(&sh_x[hb ^ 1][xrow][xc4 * 4]) = xreg;

        // ---- Cluster barrier: orders DSMEM h stores for next step ----
        if (t < TT - 1) CLUSTER_SYNC();
    }
}

// ---------------- Output projection ----------------
#define NTH_O 256
#define KC 64

__global__ void __launch_bounds__(NTH_O) rnn_output(
    const float* __restrict__ Wout,  // [O][H]
    const float* __restrict__ bout,  // [O]
    float* __restrict__ out)         // [B][T][O]
{
    const int t = blockIdx.x;
    __shared__ float sH[BB][KC + 4];
    __shared__ float sW[OO][KC + 4];

    const int tid = threadIdx.x;
    const int og = tid & 15;
    const int bg = tid >> 4;

    float acc[4][4];
#pragma unroll
    for (int i = 0; i < 4; i++)
#pragma unroll
        for (int j = 0; j < 4; j++) acc[i][j] = 0.0f;

    const float* hrow = g_hist + (size_t)t * BB * HH;

    for (int kc = 0; kc < HH; kc += KC) {
        for (int idx = tid; idx < BB * (KC / 4); idx += NTH_O) {
            int row = idx / (KC / 4);
            int c4  = idx % (KC / 4);
            float4 v = *reinterpret_cast<const float4*>(hrow + (size_t)row * HH + kc + c4 * 4);
            sH[row][c4 * 4 + 0] = v.x; sH[row][c4 * 4 + 1] = v.y;
            sH[row][c4 * 4 + 2] = v.z; sH[row][c4 * 4 + 3] = v.w;
        }
        for (int idx = tid; idx < OO * (KC / 4); idx += NTH_O) {
            int row = idx / (KC / 4);
            int c4  = idx % (KC / 4);
            float4 v = *reinterpret_cast<const float4*>(Wout + (size_t)row * HH + kc + c4 * 4);
            sW[row][c4 * 4 + 0] = v.x; sW[row][c4 * 4 + 1] = v.y;
            sW[row][c4 * 4 + 2] = v.z; sW[row][c4 * 4 + 3] = v.w;
        }
        __syncthreads();

#pragma unroll
        for (int k = 0; k < KC; k += 4) {
            float4 hv[4], wv[4];
#pragma unroll
            for (int bb = 0; bb < 4; bb++)
                hv[bb] = *reinterpret_cast<const float4*>(&sH[bg * 4 + bb][k]);
#pragma unroll
            for (int oo = 0; oo < 4; oo++)
                wv[oo] = *reinterpret_cast<const float4*>(&sW[og * 4 + oo][k]);
#pragma unroll
            for (int bb = 0; bb < 4; bb++)
#pragma unroll
                for (int oo = 0; oo < 4; oo++) {
                    acc[bb][oo] = fmaf(hv[bb].x, wv[oo].x, acc[bb][oo]);
                    acc[bb][oo] = fmaf(hv[bb].y, wv[oo].y, acc[bb][oo]);
                    acc[bb][oo] = fmaf(hv[bb].z, wv[oo].z, acc[bb][oo]);
                    acc[bb][oo] = fmaf(hv[bb].w, wv[oo].w, acc[bb][oo]);
                }
        }
        __syncthreads();
    }

#pragma unroll
    for (int oo = 0; oo < 4; oo++) {
        float bo = __ldg(bout + og * 4 + oo);
#pragma unroll
        for (int bb = 0; bb < 4; bb++) {
            int b = bg * 4 + bb;
            int o = og * 4 + oo;
            out[(size_t)b * TT * OO + (size_t)t * OO + o] = acc[bb][oo] + bo;
        }
    }
}

__global__ void copy_hfinal(float* __restrict__ dst) {
    int i = blockIdx.x * blockDim.x + threadIdx.x;
    if (i < BB * HH) dst[i] = g_hist[(size_t)(TT - 1) * BB * HH + i];
}

extern "C" void kernel_launch(void* const* d_in, const int* in_sizes, int n_in,
                              void* d_out, int out_size) {
    const float* x    = (const float*)d_in[0];
    const float* h0   = (const float*)d_in[1];
    const float* Win  = (const float*)d_in[2];
    const float* Wrec = (const float*)d_in[3];
    const float* bias = (const float*)d_in[4];
    const float* Wout = (const float*)d_in[5];
    const float* bout = (const float*)d_in[6];
    float* out = (float*)d_out;

    rnn_recurrent<<<GRID_R, NTH_R>>>(x, h0, Win, Wrec, bias);
    rnn_output<<<TT, NTH_O>>>(Wout, bout, out);
    if (out_size >= BB * TT * OO + BB * HH) {
        copy_hfinal<<<(BB * HH + 255) / 256, 256>>>(out + (size_t)BB * TT * OO);
    }
}

// round 7
// speedup vs baseline: 1.3973x; 1.3973x over previous
#include <cuda_runtime.h>
#include <math.h>

// Problem constants
#define BB 64
#define TT 512
#define II 128
#define HH 512
#define OO 64
#define ALPHA 0.1f

// Recurrent config (R5-proven skeleton): grid 128 = 16 j-blocks x 8 batch-blocks.
// CTA owns 32 j x 8 batches; 16 warps = 8 jgrp x 2 bgrp; warp tile 4j x 4b;
// lanes partition k 32-way (16 k each, as 8 f32x2 pairs).
#define GRID_R 128
#define NTH_R 512
#define NJB 16   // j-blocks per batch-block (barrier group size)

__device__ float g_hist[(size_t)TT * BB * HH];
__device__ unsigned g_cnt8[8 * 32];   // per-batch-block counters, 128B apart

__global__ void reset_kernel() {
    int i = threadIdx.x;
    if (i < 8 * 32) g_cnt8[i] = 0u;
}

__device__ __forceinline__ float fast_tanh(float v) {
    float e = __expf(2.0f * v);
    return (e - 1.0f) / (e + 1.0f);
}
__device__ __forceinline__ unsigned long long pack2(float a, float b) {
    unsigned long long r;
    asm("mov.b64 %0, {%1,%2};" : "=l"(r) : "f"(a), "f"(b));
    return r;
}
__device__ __forceinline__ void fma2(unsigned long long& d,
                                     unsigned long long a,
                                     unsigned long long b) {
    asm("fma.rn.f32x2 %0, %1, %2, %3;" : "=l"(d) : "l"(a), "l"(b), "l"(d));
}
__device__ __forceinline__ float hadd2(unsigned long long v) {
    float lo, hi;
    asm("mov.b64 {%0,%1}, %2;" : "=f"(lo), "=f"(hi) : "l"(v));
    return lo + hi;
}
__device__ __forceinline__ void cpasync16(unsigned saddr, const void* g) {
    asm volatile("cp.async.cg.shared.global [%0], [%1], 16;" :: "r"(saddr), "l"(g));
}
#define CP_COMMIT() asm volatile("cp.async.commit_group;" ::: "memory")
#define CP_WAIT0()  asm volatile("cp.async.wait_group 0;" ::: "memory")

__global__ void __launch_bounds__(NTH_R, 1) rnn_recurrent(
    const float* __restrict__ x,     // [B][T][I]
    const float* __restrict__ h0,    // [B][H]
    const float* __restrict__ Win,   // [H][I]
    const float* __restrict__ Wrec,  // [H][H]
    const float* __restrict__ bias)  // [H]
{
    __shared__ float sh_h[8][HH];        // 8 batches of h_prev (16 KB)
    __shared__ float sh_x[2][8][II];     // double-buffered x_t (8 KB)

    const int tid  = threadIdx.x;
    const int warp = tid >> 5;
    const int lane = tid & 31;

    const int jb   = blockIdx.x & 15;    // j-block
    const int bblk = blockIdx.x >> 4;    // batch-block (barrier group)
    const int j0   = jb * 32;
    const int b0   = bblk * 8;

    const int jw = warp & 7;             // warp's j-group (4 j)
    const int bw = warp >> 3;            // warp's b-group (4 b)
    const int jbase = jw * 4;
    const int bbase = bw * 4;

    unsigned* my_cnt = &g_cnt8[bblk * 32];

    // ---- Preload + pack weights ONCE: k-paired f32x2 (low = even k) ----
    unsigned long long wr2[4][8];   // wr2[jj][2c+s]: (W[j][c*128+lane*4+2s], W[.. +2s+1])
    unsigned long long wi2[4][2];   // wi2[jj][p]:   (Win[j][lane*4+2p], [.. +2p+1])
#pragma unroll
    for (int jj = 0; jj < 4; jj++) {
        const float* wrow = Wrec + (size_t)(j0 + jbase + jj) * HH;
#pragma unroll
        for (int c = 0; c < 4; c++) {
            float4 w = *reinterpret_cast<const float4*>(wrow + c * 128 + lane * 4);
            wr2[jj][2 * c]     = pack2(w.x, w.y);
            wr2[jj][2 * c + 1] = pack2(w.z, w.w);
        }
        float4 q = *reinterpret_cast<const float4*>(Win + (size_t)(j0 + jbase + jj) * II + lane * 4);
        wi2[jj][0] = pack2(q.x, q.y);
        wi2[jj][1] = pack2(q.z, q.w);
    }

    // Reduction ownership (R6-verified): lane bits -> idx = 8*b0+4*b1+2*b2+b3
    const int e = lane & 15;
    const int bb_e = 2 * (e & 1) + ((e >> 1) & 1);
    const int jj_e = 2 * ((e >> 2) & 1) + ((e >> 3) & 1);
    const int jg   = j0 + jbase + jj_e;
    const float bj = bias[jg];

    // ---- Prologue: stage h0 and x_0 synchronously ----
    {
        int idx = tid;
#pragma unroll
        for (int r = 0; r < 2; r++, idx += NTH_R) {
            int row = idx >> 7, c4 = idx & 127;
            float4 v4 = __ldg(reinterpret_cast<const float4*>(h0 + (size_t)(b0 + row) * HH + c4 * 4));
            *reinterpret_cast<float4*>(&sh_h[row][c4 * 4]) = v4;
        }
        if (tid < 256) {
            int xrow = tid >> 5, xc4 = tid & 31;
            float4 xv = __ldg(reinterpret_cast<const float4*>(
                x + ((size_t)(b0 + xrow) * TT + 0) * II + xc4 * 4));
            *reinterpret_cast<float4*>(&sh_x[0][xrow][xc4 * 4]) = xv;
        }
    }
    __syncthreads();

    for (int t = 0; t < TT; ++t) {
        const int xb = t & 1;

        // ---- Compute: acc2[bb*4+jj] (f32x2: even-k lane / odd-k lane) ----
        unsigned long long acc2[16];
#pragma unroll
        for (int i = 0; i < 16; i++) acc2[i] = 0ULL;

#pragma unroll
        for (int bb = 0; bb < 4; bb++) {
            const int bl = bbase + bb;
#pragma unroll
            for (int c = 0; c < 4; c++) {
                ulonglong2 hv = *reinterpret_cast<const ulonglong2*>(&sh_h[bl][c * 128 + lane * 4]);
#pragma unroll
                for (int jj = 0; jj < 4; jj++) {
                    fma2(acc2[bb * 4 + jj], hv.x, wr2[jj][2 * c]);
                    fma2(acc2[bb * 4 + jj], hv.y, wr2[jj][2 * c + 1]);
                }
            }
            ulonglong2 xv = *reinterpret_cast<const ulonglong2*>(&sh_x[xb][bl][lane * 4]);
#pragma unroll
            for (int jj = 0; jj < 4; jj++) {
                fma2(acc2[bb * 4 + jj], xv.x, wi2[jj][0]);
                fma2(acc2[bb * 4 + jj], xv.y, wi2[jj][1]);
            }
        }

        // ---- Horizontal add (even+odd k), then 16-shfl log-halving reduction ----
        float v[16];
#pragma unroll
        for (int i = 0; i < 16; i++) v[i] = hadd2(acc2[i]);

#pragma unroll
        for (int i = 0; i < 8; i++) {
            float send = (lane & 1) ? v[i] : v[i + 8];
            float r = __shfl_xor_sync(0xffffffffu, send, 1);
            v[i] = ((lane & 1) ? v[i + 8] : v[i]) + r;
        }
#pragma unroll
        for (int i = 0; i < 4; i++) {
            float send = (lane & 2) ? v[i] : v[i + 4];
            float r = __shfl_xor_sync(0xffffffffu, send, 2);
            v[i] = ((lane & 2) ? v[i + 4] : v[i]) + r;
        }
#pragma unroll
        for (int i = 0; i < 2; i++) {
            float send = (lane & 4) ? v[i] : v[i + 2];
            float r = __shfl_xor_sync(0xffffffffu, send, 4);
            v[i] = ((lane & 4) ? v[i + 2] : v[i]) + r;
        }
        {
            float send = (lane & 8) ? v[0] : v[1];
            float r = __shfl_xor_sync(0xffffffffu, send, 8);
            v[0] = ((lane & 8) ? v[1] : v[0]) + r;
        }
        v[0] += __shfl_xor_sync(0xffffffffu, v[0], 16);

        // ---- Epilogue: lanes 0..15 own one (b, j) ----
        if (lane < 16) {
            const int bl = bbase + bb_e;
            float hold = sh_h[bl][jg];
            float pre  = v[0] + bj;
            float hnew = (1.0f - ALPHA) * hold + ALPHA * fast_tanh(pre);
            __stcg(g_hist + (size_t)t * BB * HH + (size_t)(b0 + bl) * HH + jg, hnew);
        }

        // ---- Issue x_{t+1} async into other buffer (h-independent, fully hidden) ----
        if (t + 1 < TT) {
            if (tid < 256) {
                int xrow = tid >> 5, xc4 = tid & 31;
                unsigned sa = (unsigned)__cvta_generic_to_shared(&sh_x[xb ^ 1][xrow][xc4 * 4]);
                cpasync16(sa, x + ((size_t)(b0 + xrow) * TT + (t + 1)) * II + xc4 * 4);
            }
            CP_COMMIT();
        }

        __syncthreads();
        if (t < TT - 1) {
            // ---- Per-batch-block barrier (R5-proven) ----
            if (tid == 0) {
                __threadfence();
                atomicAdd(my_cnt, 1u);
                const unsigned target = (unsigned)(t + 1) * NJB;
                while (*((volatile unsigned*)my_cnt) < target) { }
            }
            __syncthreads();

            // ---- Stage h_t (just produced) via cp.async ----
            {
                const float* hsrc = g_hist + (size_t)t * BB * HH;
                int idx = tid;
#pragma unroll
                for (int r = 0; r < 2; r++, idx += NTH_R) {
                    int row = idx >> 7, c4 = idx & 127;
                    unsigned sa = (unsigned)__cvta_generic_to_shared(&sh_h[row][c4 * 4]);
                    cpasync16(sa, hsrc + (size_t)(b0 + row) * HH + c4 * 4);
                }
            }
            CP_COMMIT();
            CP_WAIT0();
            __syncthreads();
        }
    }
}

// ---------------- Output projection ----------------
#define NTH_O 256
#define KC 64

__global__ void __launch_bounds__(NTH_O) rnn_output(
    const float* __restrict__ Wout,  // [O][H]
    const float* __restrict__ bout,  // [O]
    float* __restrict__ out)         // [B][T][O]
{
    const int t = blockIdx.x;
    __shared__ float sH[BB][KC + 4];
    __shared__ float sW[OO][KC + 4];

    const int tid = threadIdx.x;
    const int og = tid & 15;
    const int bg = tid >> 4;

    float acc[4][4];
#pragma unroll
    for (int i = 0; i < 4; i++)
#pragma unroll
        for (int j = 0; j < 4; j++) acc[i][j] = 0.0f;

    const float* hrow = g_hist + (size_t)t * BB * HH;

    for (int kc = 0; kc < HH; kc += KC) {
        for (int idx = tid; idx < BB * (KC / 4); idx += NTH_O) {
            int row = idx / (KC / 4);
            int c4  = idx % (KC / 4);
            float4 v = *reinterpret_cast<const float4*>(hrow + (size_t)row * HH + kc + c4 * 4);
            sH[row][c4 * 4 + 0] = v.x; sH[row][c4 * 4 + 1] = v.y;
            sH[row][c4 * 4 + 2] = v.z; sH[row][c4 * 4 + 3] = v.w;
        }
        for (int idx = tid; idx < OO * (KC / 4); idx += NTH_O) {
            int row = idx / (KC / 4);
            int c4  = idx % (KC / 4);
            float4 v = *reinterpret_cast<const float4*>(Wout + (size_t)row * HH + kc + c4 * 4);
            sW[row][c4 * 4 + 0] = v.x; sW[row][c4 * 4 + 1] = v.y;
            sW[row][c4 * 4 + 2] = v.z; sW[row][c4 * 4 + 3] = v.w;
        }
        __syncthreads();

#pragma unroll
        for (int k = 0; k < KC; k += 4) {
            float4 hv[4], wv[4];
#pragma unroll
            for (int bb = 0; bb < 4; bb++)
                hv[bb] = *reinterpret_cast<const float4*>(&sH[bg * 4 + bb][k]);
#pragma unroll
            for (int oo = 0; oo < 4; oo++)
                wv[oo] = *reinterpret_cast<const float4*>(&sW[og * 4 + oo][k]);
#pragma unroll
            for (int bb = 0; bb < 4; bb++)
#pragma unroll
                for (int oo = 0; oo < 4; oo++) {
                    acc[bb][oo] = fmaf(hv[bb].x, wv[oo].x, acc[bb][oo]);
                    acc[bb][oo] = fmaf(hv[bb].y, wv[oo].y, acc[bb][oo]);
                    acc[bb][oo] = fmaf(hv[bb].z, wv[oo].z, acc[bb][oo]);
                    acc[bb][oo] = fmaf(hv[bb].w, wv[oo].w, acc[bb][oo]);
                }
        }
        __syncthreads();
    }

#pragma unroll
    for (int oo = 0; oo < 4; oo++) {
        float bo = __ldg(bout + og * 4 + oo);
#pragma unroll
        for (int bb = 0; bb < 4; bb++) {
            int b = bg * 4 + bb;
            int o = og * 4 + oo;
            out[(size_t)b * TT * OO + (size_t)t * OO + o] = acc[bb][oo] + bo;
        }
    }
}

__global__ void copy_hfinal(float* __restrict__ dst) {
    int i = blockIdx.x * blockDim.x + threadIdx.x;
    if (i < BB * HH) dst[i] = g_hist[(size_t)(TT - 1) * BB * HH + i];
}

extern "C" void kernel_launch(void* const* d_in, const int* in_sizes, int n_in,
                              void* d_out, int out_size) {
    const float* x    = (const float*)d_in[0];
    const float* h0   = (const float*)d_in[1];
    const float* Win  = (const float*)d_in[2];
    const float* Wrec = (const float*)d_in[3];
    const float* bias = (const float*)d_in[4];
    const float* Wout = (const float*)d_in[5];
    const float* bout = (const float*)d_in[6];
    float* out = (float*)d_out;

    reset_kernel<<<1, 256>>>();
    rnn_recurrent<<<GRID_R, NTH_R>>>(x, h0, Win, Wrec, bias);
    rnn_output<<<TT, NTH_O>>>(Wout, bout, out);
    if (out_size >= BB * TT * OO + BB * HH) {
        copy_hfinal<<<(BB * HH + 255) / 256, 256>>>(out + (size_t)BB * TT * OO);
    }
}